// round 11
// baseline (speedup 1.0000x reference)
#include <cuda_runtime.h>
#include <cuda_fp16.h>
#include <cstdint>

// ====================== tile/pipeline constants ======================
// CTA: 128 threads (4 warps 2x2), tile 128 couts x 112 pixels (2 output rows)
#define STG      15360            // per-stage smem: A 8192 (128x64B) + B 7168 (112x64B)
#define STAGES   4
#define SMEM_DYN (STAGES * STG + 128)

// ====================== device scratch ======================
__device__ __align__(16) __half g_x[(size_t)32 * 58 * 58 * 256];  // padded NHWC fp16
__device__ __align__(16) __half g_w[(size_t)9 * 256 * 256];       // [tap][co][ci] = +-1

// ====================== helpers ======================
__device__ __forceinline__ uint32_t smem_u32(const void* p) {
    uint32_t a;
    asm("{ .reg .u64 t; cvta.to.shared.u64 t, %1; cvt.u32.u64 %0, t; }" : "=r"(a) : "l"(p));
    return a;
}
__device__ __forceinline__ void cp16(uint32_t d, const void* s) {
    asm volatile("cp.async.cg.shared.global [%0], [%1], 16;" :: "r"(d), "l"(s) : "memory");
}
__device__ __forceinline__ void ldsm_x4(uint32_t* r, uint32_t a) {
    asm volatile("ldmatrix.sync.aligned.m8n8.x4.shared.b16 {%0,%1,%2,%3}, [%4];"
                 : "=r"(r[0]), "=r"(r[1]), "=r"(r[2]), "=r"(r[3]) : "r"(a));
}
__device__ __forceinline__ void ldsm_x2(uint32_t* r, uint32_t a) {
    asm volatile("ldmatrix.sync.aligned.m8n8.x2.shared.b16 {%0,%1}, [%2];"
                 : "=r"(r[0]), "=r"(r[1]) : "r"(a));
}
__device__ __forceinline__ void mma16816(float* c, uint32_t a0, uint32_t a1, uint32_t a2,
                                         uint32_t a3, uint32_t b0, uint32_t b1) {
    asm volatile(
        "mma.sync.aligned.m16n8k16.row.col.f32.f16.f16.f32 "
        "{%0,%1,%2,%3}, {%4,%5,%6,%7}, {%8,%9}, {%0,%1,%2,%3};"
        : "+f"(c[0]), "+f"(c[1]), "+f"(c[2]), "+f"(c[3])
        : "r"(a0), "r"(a1), "r"(a2), "r"(a3), "r"(b0), "r"(b1));
}

// ====================== prep kernels ======================
__global__ void zero_border_kernel() {
    const int n = blockIdx.x;                       // 32 images
    __half* xb = g_x + (size_t)n * 861184;
    for (int c = threadIdx.x; c < 7296; c += 256) { // 228 border px * 32 uint4
        int px = c >> 5, q = c & 31;
        int h, w;
        if (px < 58)       { h = 0;        w = px; }
        else if (px < 116) { h = 57;       w = px - 58; }
        else if (px < 172) { h = px - 115; w = 0; }
        else               { h = px - 171; w = 57; }
        reinterpret_cast<uint4*>(xb + ((size_t)h * 58 + w) * 256)[q] =
            make_uint4(0u, 0u, 0u, 0u);
    }
}

// x NCHW f32 -> g_x padded NHWC fp16 (linear ci). grid 32*56*2, 256 thr.
__global__ void prep_x_kernel(const float* __restrict__ x) {
    __shared__ float tile[128][57];
    const int b  = blockIdx.x;
    const int ch = b & 1;
    const int h  = (b >> 1) % 56;
    const int n  = (b >> 1) / 56;
    const float* src = x + (size_t)(n * 256 + ch * 128) * 3136 + h * 56;
    for (int i = threadIdx.x; i < 128 * 56; i += 256) {
        int ci = i / 56, w = i - 56 * ci;
        tile[ci][w] = src[(size_t)ci * 3136 + w];
    }
    __syncthreads();
    __half* dst = g_x + (size_t)n * 861184 + ((h + 1) * 58 + 1) * 256;
    for (int j = threadIdx.x; j < 64 * 56; j += 256) {
        int w  = j >> 6, cp = j & 63;
        int ci = ch * 128 + 2 * cp;
        __half2 v = __floats2half2_rn(tile[2 * cp][w], tile[2 * cp + 1][w]);
        *reinterpret_cast<__half2*>(dst + (size_t)w * 256 + ci) = v;
    }
}

// weight [co][ci][3][3] f32 -> g_w[tap][co][ci] = +-1 fp16. grid 2304, 256 thr.
__global__ void prep_w_kernel(const float* __restrict__ w) {
    int idx = blockIdx.x * 256 + threadIdx.x;             // co*2304 + ci*9 + tap
    int co  = idx / 2304;
    int r   = idx - co * 2304;
    int ci  = r / 9;
    int tap = r - ci * 9;
    g_w[(size_t)(tap * 256 + co) * 256 + ci] = __float2half(w[idx] >= 0.f ? 1.f : -1.f);
}

// ====================== main kernel ======================
// grid 1792 = 2 cout-halves * 28 row-pairs * 32 images; 128 threads (4 warps 2x2).
// Warp tile 64x56: 4 m16-frags x 7 n8-frags, 2 ksteps per 32-ci stage.
// Smem swizzle: 64B rows, 16B bank index = chunk ^ ((row>>1)&3)  (ldmatrix conflict-free)
// Barrier is placed BETWEEN ks1 LDSM and ks1 MMA so the sync overlaps the queued
// ks0 HMMAs and every warp leaves the barrier with a full fragment set to issue.
__global__ void __launch_bounds__(128, 3)
bconv_main_kernel(const float* __restrict__ bias, float* __restrict__ out) {
    extern __shared__ char dsm[];
    const uint32_t base = (smem_u32(dsm) + 127u) & ~127u;

    const int tid  = threadIdx.x;
    const int lane = tid & 31;
    const int wid  = tid >> 5;
    const int g    = lane >> 2;
    const int t    = lane & 3;
    const int wm   = wid >> 1;     // 0..1  (m warp half)
    const int wn   = wid & 1;      // 0..1  (output row within pair)

    const int bid = blockIdx.x;
    const int mb  = bid & 1;
    const int rp  = (bid >> 1) % 28;
    const int n   = bid / 56;
    const int h0  = rp * 2;

    const __half* xn = g_x + (size_t)n * 861184;

    // ---- per-thread cp.async chunk tables (16B chunks) ----
    uint32_t aD[4], aG[4], bD[4], bG[4];
#pragma unroll
    for (int i = 0; i < 4; i++) {
        int c   = tid + 128 * i;          // A chunk 0..511
        int row = c >> 2, cb = c & 3;
        aD[i] = (uint32_t)(row * 64 + ((cb ^ ((row >> 1) & 3)) << 4));
        aG[i] = (uint32_t)((mb * 128 + row) * 256 + cb * 8);
    }
#pragma unroll
    for (int i = 0; i < 4; i++) {
        int c    = (i < 3) ? (tid + 128 * i) : (384 + tid);   // B chunk 0..447 (i==3: tid<64)
        int prow = c >> 2, cb = c & 3;
        int pr   = prow / 56, pw = prow - 56 * pr;
        bD[i] = (uint32_t)(8192 + prow * 64 + ((cb ^ ((prow >> 1) & 3)) << 4));
        bG[i] = (uint32_t)(((h0 + pr) * 58 + pw) * 256 + cb * 8);
    }

    auto load_stage = [&](int s, uint32_t sb) {
        int tap = s >> 3, kc = s & 7;
        int dh  = tap / 3, dw = tap - 3 * dh;
        uint32_t ad = (uint32_t)(tap * 65536 + kc * 32);
        uint32_t bd = (uint32_t)((dh * 58 + dw) * 256 + kc * 32);
        cp16(sb + aD[0], g_w + aG[0] + ad);
        cp16(sb + aD[1], g_w + aG[1] + ad);
        cp16(sb + aD[2], g_w + aG[2] + ad);
        cp16(sb + aD[3], g_w + aG[3] + ad);
        cp16(sb + bD[0], xn + bG[0] + bd);
        cp16(sb + bD[1], xn + bG[1] + bd);
        cp16(sb + bD[2], xn + bG[2] + bd);
        if (tid < 64) cp16(sb + bD[3], xn + bG[3] + bd);
        asm volatile("cp.async.commit_group;" ::: "memory");
    };

    // ---- ldmatrix lane addresses (kstep 0; kstep 1 = XOR 0x20) ----
    uint32_t rA[4];
    {
        int rl   = (lane & 7) + ((lane >> 3) & 1) * 8;
        int half = lane >> 4;
#pragma unroll
        for (int mi = 0; mi < 4; mi++) {
            int row = wm * 64 + mi * 16 + rl;
            rA[mi] = (uint32_t)(row * 64 + ((half ^ ((row >> 1) & 3)) << 4));
        }
    }
    uint32_t rB[4];
    {
        int pl   = (lane & 7) + (lane >> 4) * 8;
        int half = (lane >> 3) & 1;
#pragma unroll
        for (int pi = 0; pi < 3; pi++) {
            int pix = wn * 56 + pi * 16 + pl;
            rB[pi] = (uint32_t)(8192 + pix * 64 + ((half ^ ((pix >> 1) & 3)) << 4));
        }
        int pix6 = wn * 56 + 48 + (lane & 7);
        rB[3] = (uint32_t)(8192 + pix6 * 64 + ((half ^ ((pix6 >> 1) & 3)) << 4));
    }

    float acc[4][7][4];
#pragma unroll
    for (int mi = 0; mi < 4; mi++)
#pragma unroll
        for (int ni = 0; ni < 7; ni++)
#pragma unroll
            for (int k = 0; k < 4; k++) acc[mi][ni][k] = 0.f;

    // ---- prologue: stages 0..2 ----
    for (int s = 0; s < 3; s++) load_stage(s, base + s * STG);
    asm volatile("cp.async.wait_group 2;" ::: "memory");
    __syncthreads();

    // ---- mainloop: 72 stages, 4 buffers ----
    for (int s = 0; s < 72; s++) {
        if (s + 3 < 72) load_stage(s + 3, base + ((s + 3) & 3) * STG);
        else asm volatile("cp.async.commit_group;" ::: "memory");

        const uint32_t sb = base + (s & 3) * STG;

        // ---- kstep 0: LDSM + MMA ----
        {
            uint32_t a[4][4];
#pragma unroll
            for (int mi = 0; mi < 4; mi++) ldsm_x4(a[mi], sb + rA[mi]);
#pragma unroll
            for (int pi = 0; pi < 3; pi++) {
                uint32_t b[4];
                ldsm_x4(b, sb + rB[pi]);
#pragma unroll
                for (int mi = 0; mi < 4; mi++) {
                    mma16816(acc[mi][2 * pi],     a[mi][0], a[mi][1], a[mi][2], a[mi][3], b[0], b[1]);
                    mma16816(acc[mi][2 * pi + 1], a[mi][0], a[mi][1], a[mi][2], a[mi][3], b[2], b[3]);
                }
            }
            uint32_t b6[2];
            ldsm_x2(b6, sb + rB[3]);
#pragma unroll
            for (int mi = 0; mi < 4; mi++)
                mma16816(acc[mi][6], a[mi][0], a[mi][1], a[mi][2], a[mi][3], b6[0], b6[1]);
        }

        // ---- kstep 1: LDSM, then barrier (overlaps ks0 MMA drain), then MMA ----
        {
            uint32_t a[4][4], b0[4], b1[4], b2[4], b6[2];
#pragma unroll
            for (int mi = 0; mi < 4; mi++) ldsm_x4(a[mi], sb + (rA[mi] ^ 0x20u));
            ldsm_x4(b0, sb + (rB[0] ^ 0x20u));
            ldsm_x4(b1, sb + (rB[1] ^ 0x20u));
            ldsm_x4(b2, sb + (rB[2] ^ 0x20u));
            ldsm_x2(b6, sb + (rB[3] ^ 0x20u));

            asm volatile("cp.async.wait_group 2;" ::: "memory");
            __syncthreads();

#pragma unroll
            for (int mi = 0; mi < 4; mi++) {
                mma16816(acc[mi][0], a[mi][0], a[mi][1], a[mi][2], a[mi][3], b0[0], b0[1]);
                mma16816(acc[mi][1], a[mi][0], a[mi][1], a[mi][2], a[mi][3], b0[2], b0[3]);
            }
#pragma unroll
            for (int mi = 0; mi < 4; mi++) {
                mma16816(acc[mi][2], a[mi][0], a[mi][1], a[mi][2], a[mi][3], b1[0], b1[1]);
                mma16816(acc[mi][3], a[mi][0], a[mi][1], a[mi][2], a[mi][3], b1[2], b1[3]);
            }
#pragma unroll
            for (int mi = 0; mi < 4; mi++) {
                mma16816(acc[mi][4], a[mi][0], a[mi][1], a[mi][2], a[mi][3], b2[0], b2[1]);
                mma16816(acc[mi][5], a[mi][0], a[mi][1], a[mi][2], a[mi][3], b2[2], b2[3]);
            }
#pragma unroll
            for (int mi = 0; mi < 4; mi++)
                mma16816(acc[mi][6], a[mi][0], a[mi][1], a[mi][2], a[mi][3], b6[0], b6[1]);
        }
    }

    // ---- epilogue: registers -> gmem (float2), + binarized bias ----
    const int h = h0 + wn;
#pragma unroll
    for (int mi = 0; mi < 4; mi++) {
        int mlo = mb * 128 + wm * 64 + mi * 16 + g;
        float blo = (bias[mlo]     >= 0.f) ? 1.f : -1.f;
        float bhi = (bias[mlo + 8] >= 0.f) ? 1.f : -1.f;
        size_t olo = ((size_t)(n * 256 + mlo)) * 3136 + h * 56;
        size_t ohi = olo + (size_t)8 * 3136;
#pragma unroll
        for (int ni = 0; ni < 7; ni++) {
            int w = ni * 8 + 2 * t;
            float2 v0 = make_float2(acc[mi][ni][0] + blo, acc[mi][ni][1] + blo);
            float2 v1 = make_float2(acc[mi][ni][2] + bhi, acc[mi][ni][3] + bhi);
            *reinterpret_cast<float2*>(out + olo + w) = v0;
            *reinterpret_cast<float2*>(out + ohi + w) = v1;
        }
    }
}

// ====================== launch ======================
extern "C" void kernel_launch(void* const* d_in, const int* in_sizes, int n_in,
                              void* d_out, int out_size) {
    const float* x    = (const float*)d_in[0];
    const float* w    = (const float*)d_in[1];
    const float* bias = (const float*)d_in[2];
    float* out        = (float*)d_out;

    cudaFuncSetAttribute(bconv_main_kernel,
                         cudaFuncAttributeMaxDynamicSharedMemorySize, SMEM_DYN);

    zero_border_kernel<<<32, 256>>>();
    prep_x_kernel<<<32 * 56 * 2, 256>>>(x);
    prep_w_kernel<<<2304, 256>>>(w);
    bconv_main_kernel<<<1792, 128, SMEM_DYN>>>(bias, out);
}

// round 12
// speedup vs baseline: 1.1390x; 1.1390x over previous
#include <cuda_runtime.h>
#include <cuda_fp16.h>
#include <cstdint>

// ====================== tile/pipeline constants ======================
// CTA: 128 threads (4 warps 2x2), tile 128 couts x 112 pixels (2 output rows)
// Superstage = 64 ci: A 16384 B (128 rows x 128B) + B 14336 B (112 rows x 128B)
#define STG      30720
#define STAGES   2
#define SMEM_DYN (STAGES * STG + 128)

// ====================== device scratch ======================
__device__ __align__(16) __half g_x[(size_t)32 * 58 * 58 * 256];  // padded NHWC fp16
__device__ __align__(16) __half g_w[(size_t)9 * 256 * 256];       // [tap][co][ci] = +-1

// ====================== helpers ======================
__device__ __forceinline__ uint32_t smem_u32(const void* p) {
    uint32_t a;
    asm("{ .reg .u64 t; cvta.to.shared.u64 t, %1; cvt.u32.u64 %0, t; }" : "=r"(a) : "l"(p));
    return a;
}
__device__ __forceinline__ void cp16(uint32_t d, const void* s) {
    asm volatile("cp.async.cg.shared.global [%0], [%1], 16;" :: "r"(d), "l"(s) : "memory");
}
__device__ __forceinline__ void ldsm_x4(uint32_t* r, uint32_t a) {
    asm volatile("ldmatrix.sync.aligned.m8n8.x4.shared.b16 {%0,%1,%2,%3}, [%4];"
                 : "=r"(r[0]), "=r"(r[1]), "=r"(r[2]), "=r"(r[3]) : "r"(a));
}
__device__ __forceinline__ void ldsm_x2(uint32_t* r, uint32_t a) {
    asm volatile("ldmatrix.sync.aligned.m8n8.x2.shared.b16 {%0,%1}, [%2];"
                 : "=r"(r[0]), "=r"(r[1]) : "r"(a));
}
__device__ __forceinline__ void mma16816(float* c, uint32_t a0, uint32_t a1, uint32_t a2,
                                         uint32_t a3, uint32_t b0, uint32_t b1) {
    asm volatile(
        "mma.sync.aligned.m16n8k16.row.col.f32.f16.f16.f32 "
        "{%0,%1,%2,%3}, {%4,%5,%6,%7}, {%8,%9}, {%0,%1,%2,%3};"
        : "+f"(c[0]), "+f"(c[1]), "+f"(c[2]), "+f"(c[3])
        : "r"(a0), "r"(a1), "r"(a2), "r"(a3), "r"(b0), "r"(b1));
}

// ====================== prep kernels ======================
__global__ void zero_border_kernel() {
    const int n = blockIdx.x;                       // 32 images
    __half* xb = g_x + (size_t)n * 861184;
    for (int c = threadIdx.x; c < 7296; c += 256) { // 228 border px * 32 uint4
        int px = c >> 5, q = c & 31;
        int h, w;
        if (px < 58)       { h = 0;        w = px; }
        else if (px < 116) { h = 57;       w = px - 58; }
        else if (px < 172) { h = px - 115; w = 0; }
        else               { h = px - 171; w = 57; }
        reinterpret_cast<uint4*>(xb + ((size_t)h * 58 + w) * 256)[q] =
            make_uint4(0u, 0u, 0u, 0u);
    }
}

// x NCHW f32 -> g_x padded NHWC fp16 (linear ci). grid 32*56*2, 256 thr.
__global__ void prep_x_kernel(const float* __restrict__ x) {
    __shared__ float tile[128][57];
    const int b  = blockIdx.x;
    const int ch = b & 1;
    const int h  = (b >> 1) % 56;
    const int n  = (b >> 1) / 56;
    const float* src = x + (size_t)(n * 256 + ch * 128) * 3136 + h * 56;
    for (int i = threadIdx.x; i < 128 * 56; i += 256) {
        int ci = i / 56, w = i - 56 * ci;
        tile[ci][w] = src[(size_t)ci * 3136 + w];
    }
    __syncthreads();
    __half* dst = g_x + (size_t)n * 861184 + ((h + 1) * 58 + 1) * 256;
    for (int j = threadIdx.x; j < 64 * 56; j += 256) {
        int w  = j >> 6, cp = j & 63;
        int ci = ch * 128 + 2 * cp;
        __half2 v = __floats2half2_rn(tile[2 * cp][w], tile[2 * cp + 1][w]);
        *reinterpret_cast<__half2*>(dst + (size_t)w * 256 + ci) = v;
    }
}

// weight [co][ci][3][3] f32 -> g_w[tap][co][ci] = +-1 fp16. grid 2304, 256 thr.
__global__ void prep_w_kernel(const float* __restrict__ w) {
    int idx = blockIdx.x * 256 + threadIdx.x;             // co*2304 + ci*9 + tap
    int co  = idx / 2304;
    int r   = idx - co * 2304;
    int ci  = r / 9;
    int tap = r - ci * 9;
    g_w[(size_t)(tap * 256 + co) * 256 + ci] = __float2half(w[idx] >= 0.f ? 1.f : -1.f);
}

// ====================== main kernel ======================
// grid 1792 = 2 cout-halves * 28 row-pairs * 32 images; 128 threads (4 warps 2x2).
// Warp tile 64x56: 4 m16-frags x 7 n8-frags, 4 ksteps per 64-ci superstage.
// Smem: 128B rows, 16B bank index = chunk ^ (row&7) (ldmatrix conflict-free);
// kstep k selects chunks {2k,2k+1} via address XOR (k<<5).
__global__ void __launch_bounds__(128, 3)
bconv_main_kernel(const float* __restrict__ bias, float* __restrict__ out) {
    extern __shared__ char dsm[];
    const uint32_t base = (smem_u32(dsm) + 127u) & ~127u;

    const int tid  = threadIdx.x;
    const int lane = tid & 31;
    const int wid  = tid >> 5;
    const int g    = lane >> 2;
    const int t    = lane & 3;
    const int wm   = wid >> 1;     // 0..1  (m warp half)
    const int wn   = wid & 1;      // 0..1  (output row within pair)

    const int bid = blockIdx.x;
    const int mb  = bid & 1;
    const int rp  = (bid >> 1) % 28;
    const int n   = bid / 56;
    const int h0  = rp * 2;

    const __half* xn = g_x + (size_t)n * 861184;

    // ---- cp.async affine bases (16B chunks; row&7 invariant across i since step=16) ----
    const int r0  = tid >> 3;                 // base row 0..15
    const int cbk = tid & 7;                  // chunk within 128B row
    const uint32_t cb8 = (uint32_t)(cbk * 8); // element offset of chunk
    const uint32_t swz = (uint32_t)((cbk ^ (r0 & 7)) << 4);
    const uint32_t aD0 = (uint32_t)(r0 * 128) + swz;
    const uint32_t bD0 = 16384u + aD0;
    const uint32_t aG0 = (uint32_t)((mb * 128 + r0) * 256) + cb8;

    auto load_ss = [&](int ss, uint32_t sb) {
        int tap = ss >> 2, kc2 = ss & 3;      // 64-ci chunk within tap
        int dh  = tap / 3, dw = tap - 3 * dh;
        const __half* wp = g_w + tap * 65536 + kc2 * 64 + aG0;
#pragma unroll
        for (int i = 0; i < 8; i++)           // A: 128 rows, this thread rows r0+16i
            cp16(sb + aD0 + (uint32_t)(i * 2048), wp + i * 4096);
        uint32_t bgc = (uint32_t)((((h0 + dh) * 58 + dw) * 256) + kc2 * 64) + cb8;
#pragma unroll
        for (int i = 0; i < 7; i++) {         // B: 112 pixel rows, rows r0+16i
            int prow = r0 + 16 * i;
            uint32_t off = bgc + (uint32_t)(prow * 256) + (prow >= 56 ? 512u : 0u);
            cp16(sb + bD0 + (uint32_t)(i * 2048), xn + off);
        }
        asm volatile("cp.async.commit_group;" ::: "memory");
    };

    // ---- ldmatrix lane addresses (kstep 0; kstep k = XOR k<<5) ----
    uint32_t rA[4];
    {
        int rl   = (lane & 7) + ((lane >> 3) & 1) * 8;
        int half = lane >> 4;
#pragma unroll
        for (int mi = 0; mi < 4; mi++) {
            int row = wm * 64 + mi * 16 + rl;
            rA[mi] = (uint32_t)(row * 128 + ((half ^ (row & 7)) << 4));
        }
    }
    uint32_t rB[4];
    {
        int pl   = (lane & 7) + (lane >> 4) * 8;
        int half = (lane >> 3) & 1;
#pragma unroll
        for (int pi = 0; pi < 3; pi++) {
            int pix = wn * 56 + pi * 16 + pl;
            rB[pi] = 16384u + (uint32_t)(pix * 128 + ((half ^ (pix & 7)) << 4));
        }
        int pix6 = wn * 56 + 48 + (lane & 7);
        rB[3] = 16384u + (uint32_t)(pix6 * 128 + ((half ^ (pix6 & 7)) << 4));
    }

    float acc[4][7][4];
#pragma unroll
    for (int mi = 0; mi < 4; mi++)
#pragma unroll
        for (int ni = 0; ni < 7; ni++)
#pragma unroll
            for (int k = 0; k < 4; k++) acc[mi][ni][k] = 0.f;

    // ---- prologue: superstage 0 ----
    load_ss(0, base);
    asm volatile("cp.async.wait_group 0;" ::: "memory");
    __syncthreads();

    // ---- mainloop: 36 superstages, 2 buffers ----
    for (int ss = 0; ss < 36; ss++) {
        if (ss < 35) load_ss(ss + 1, base + (uint32_t)(((ss + 1) & 1) * STG));

        const uint32_t sb = base + (uint32_t)((ss & 1) * STG);
#pragma unroll
        for (int k = 0; k < 4; k++) {
            const uint32_t xr = (uint32_t)(k << 5);
            uint32_t a[4][4];
#pragma unroll
            for (int mi = 0; mi < 4; mi++) ldsm_x4(a[mi], sb + (rA[mi] ^ xr));
#pragma unroll
            for (int pi = 0; pi < 3; pi++) {
                uint32_t b[4];
                ldsm_x4(b, sb + (rB[pi] ^ xr));
#pragma unroll
                for (int mi = 0; mi < 4; mi++) {
                    mma16816(acc[mi][2 * pi],     a[mi][0], a[mi][1], a[mi][2], a[mi][3], b[0], b[1]);
                    mma16816(acc[mi][2 * pi + 1], a[mi][0], a[mi][1], a[mi][2], a[mi][3], b[2], b[3]);
                }
            }
            uint32_t b6[2];
            ldsm_x2(b6, sb + (rB[3] ^ xr));
#pragma unroll
            for (int mi = 0; mi < 4; mi++)
                mma16816(acc[mi][6], a[mi][0], a[mi][1], a[mi][2], a[mi][3], b6[0], b6[1]);
        }
        asm volatile("cp.async.wait_group 0;" ::: "memory");
        __syncthreads();
    }

    // ---- epilogue: registers -> gmem (float2), + binarized bias ----
    const int h = h0 + wn;
#pragma unroll
    for (int mi = 0; mi < 4; mi++) {
        int mlo = mb * 128 + wm * 64 + mi * 16 + g;
        float blo = (bias[mlo]     >= 0.f) ? 1.f : -1.f;
        float bhi = (bias[mlo + 8] >= 0.f) ? 1.f : -1.f;
        size_t olo = ((size_t)(n * 256 + mlo)) * 3136 + h * 56;
        size_t ohi = olo + (size_t)8 * 3136;
#pragma unroll
        for (int ni = 0; ni < 7; ni++) {
            int w = ni * 8 + 2 * t;
            float2 v0 = make_float2(acc[mi][ni][0] + blo, acc[mi][ni][1] + blo);
            float2 v1 = make_float2(acc[mi][ni][2] + bhi, acc[mi][ni][3] + bhi);
            *reinterpret_cast<float2*>(out + olo + w) = v0;
            *reinterpret_cast<float2*>(out + ohi + w) = v1;
        }
    }
}

// ====================== launch ======================
extern "C" void kernel_launch(void* const* d_in, const int* in_sizes, int n_in,
                              void* d_out, int out_size) {
    const float* x    = (const float*)d_in[0];
    const float* w    = (const float*)d_in[1];
    const float* bias = (const float*)d_in[2];
    float* out        = (float*)d_out;

    cudaFuncSetAttribute(bconv_main_kernel,
                         cudaFuncAttributeMaxDynamicSharedMemorySize, SMEM_DYN);

    zero_border_kernel<<<32, 256>>>();
    prep_x_kernel<<<32 * 56 * 2, 256>>>(x);
    prep_w_kernel<<<2304, 256>>>(w);
    bconv_main_kernel<<<1792, 128, SMEM_DYN>>>(bias, out);
}